// round 12
// baseline (speedup 1.0000x reference)
#include <cuda_runtime.h>
#include <cuda_bf16.h>
#include <cuda_fp16.h>

// ChannelSelfAttention: B=4,H=512,W=256, C=2.
// s(w,u) = c0(w)*xa[u] + c1(w)*xb[u]  (biases cancel in softmax)
// A=Σe*xa, B=Σe*xb, D=Σe in f32; V applied once per thread at the end.
// exp2 via ex2.approx.f16x2: one MUFU op per PAIR of scores (halves MUFU
// pressure, the measured queueing wall). Score + accumulation stay f32.

#define WIDTH 256

typedef unsigned long long u64;
typedef unsigned int u32;

__device__ __forceinline__ u64 f2_pack(float lo, float hi) {
    u64 r; asm("mov.b64 %0, {%1,%2};" : "=l"(r) : "f"(lo), "f"(hi)); return r;
}
__device__ __forceinline__ void f2_unpack(u64 v, float& lo, float& hi) {
    asm("mov.b64 {%0,%1}, %2;" : "=f"(lo), "=f"(hi) : "l"(v));
}
__device__ __forceinline__ u64 f2_fma(u64 a, u64 b, u64 c) {
    u64 r; asm("fma.rn.f32x2 %0, %1, %2, %3;" : "=l"(r) : "l"(a), "l"(b), "l"(c)); return r;
}
__device__ __forceinline__ u64 f2_mul(u64 a, u64 b) {
    u64 r; asm("mul.rn.f32x2 %0, %1, %2;" : "=l"(r) : "l"(a), "l"(b)); return r;
}
__device__ __forceinline__ u64 f2_add(u64 a, u64 b) {
    u64 r; asm("add.rn.f32x2 %0, %1, %2;" : "=l"(r) : "l"(a), "l"(b)); return r;
}

// f32x2 -> f16x2 (lo in low half), saturating to max-finite
__device__ __forceinline__ u32 f2_to_h2_sat(u64 s) {
    float lo, hi; f2_unpack(s, lo, hi);
    u32 h;
    asm("cvt.rn.satfinite.f16x2.f32 %0, %1, %2;" : "=r"(h) : "f"(hi), "f"(lo));
    return h;
}
__device__ __forceinline__ u32 h2_min(u32 a, u32 b) {
    u32 r; asm("min.f16x2 %0, %1, %2;" : "=r"(r) : "r"(a), "r"(b)); return r;
}
__device__ __forceinline__ u32 h2_ex2(u32 a) {
    u32 r; asm("ex2.approx.f16x2 %0, %1;" : "=r"(r) : "r"(a)); return r;
}
// f16x2 -> f32x2 expand
__device__ __forceinline__ u64 h2_to_f2(u32 h) {
    float lo, hi;
    asm("{\n\t"
        ".reg .f16 l, u;\n\t"
        "mov.b32 {l, u}, %2;\n\t"
        "cvt.f32.f16 %0, l;\n\t"
        "cvt.f32.f16 %1, u;\n\t"
        "}"
        : "=f"(lo), "=f"(hi) : "r"(h));
    return f2_pack(lo, hi);
}

__global__ __launch_bounds__(WIDTH, 7) void channel_attn_kernel(
    const float* __restrict__ x1, const float* __restrict__ x2,
    const float* __restrict__ wq, const float* __restrict__ bq,
    const float* __restrict__ wk, const float* __restrict__ bk,
    const float* __restrict__ wv, const float* __restrict__ bv,
    float* __restrict__ out, int n_elem)
{
    __shared__ __align__(16) float sh[2 * WIDTH];   // [xa | xb]

    const int row  = blockIdx.x;
    const int w    = threadIdx.x;
    const int base = row * WIDTH;

    u64 c0p, c1p;
    {
        const float xa = x1[base + w];
        const float xb = x2[base + w];
        sh[w]         = xa;
        sh[WIDTH + w] = xb;

        const float q00 = __ldg(&wq[0]), q01 = __ldg(&wq[1]);
        const float q10 = __ldg(&wq[2]), q11 = __ldg(&wq[3]);
        const float k00 = __ldg(&wk[0]), k01 = __ldg(&wk[1]);
        const float k10 = __ldg(&wk[2]), k11 = __ldg(&wk[3]);
        const float bq0 = __ldg(&bq[0]), bq1 = __ldg(&bq[1]);
        // bk shifts every score of this thread equally -> cancels in softmax

        const float LOG2E = 1.4426950408889634f;
        const float a0 = fmaf(q00, xa, fmaf(q01, xb, bq0)) * LOG2E;
        const float a1 = fmaf(q10, xa, fmaf(q11, xb, bq1)) * LOG2E;
        const float c0 = fmaf(a0, k00, a1 * k10);
        const float c1 = fmaf(a0, k01, a1 * k11);
        c0p = f2_pack(c0, c0);
        c1p = f2_pack(c1, c1);
    }
    __syncthreads();

    const u32 K14 = 0x4B004B00u;   // half2(14.0, 14.0): clamp so 2^s stays finite in f16

    const unsigned sbase = (unsigned)__cvta_generic_to_shared(sh);

    u64 D = 0ull, A = 0ull, B = 0ull;

#pragma unroll 1
    for (int u0 = 0; u0 < WIDTH; u0 += 32) {
#pragma unroll
        for (int c = 0; c < 8; ++c) {        // 4 u per chunk, pairs (2c, 2c+1)
            const int off = (u0 + 4 * c) * 4;
            u64 xa01, xa23, xb01, xb23;
            asm("ld.shared.v2.b64 {%0,%1}, [%2];"
                : "=l"(xa01), "=l"(xa23) : "r"(sbase + off));
            asm("ld.shared.v2.b64 {%0,%1}, [%2];"
                : "=l"(xb01), "=l"(xb23) : "r"(sbase + off + WIDTH * 4));

            const u64 s01 = f2_fma(c0p, xa01, f2_mul(c1p, xb01));
            const u64 s23 = f2_fma(c0p, xa23, f2_mul(c1p, xb23));

            // one MUFU op per pair: exp2 of both scores in f16x2
            const u64 e01 = h2_to_f2(h2_ex2(h2_min(f2_to_h2_sat(s01), K14)));
            const u64 e23 = h2_to_f2(h2_ex2(h2_min(f2_to_h2_sat(s23), K14)));

            D = f2_add(D, f2_add(e01, e23));
            A = f2_fma(e01, xa01, f2_fma(e23, xa23, A));
            B = f2_fma(e01, xb01, f2_fma(e23, xb23, B));
        }
    }

    // ---- epilogue (state reloaded here, not live through the loop) ----
    float d0, d1, a0f, a1f, b0f, b1f;
    f2_unpack(D, d0, d1);
    f2_unpack(A, a0f, a1f);
    f2_unpack(B, b0f, b1f);
    const float Dv = d0 + d1;
    const float Av = a0f + a1f;
    const float Bv = b0f + b1f;

    const float v00 = __ldg(&wv[0]), v01 = __ldg(&wv[1]);
    const float v10 = __ldg(&wv[2]), v11 = __ldg(&wv[3]);
    const float bv0 = __ldg(&bv[0]), bv1 = __ldg(&bv[1]);
    const float xa = sh[w];
    const float xb = sh[WIDTH + w];

    const float inv = 1.0f / Dv;
    const float n0  = fmaf(v00, Av, fmaf(v01, Bv, bv0 * Dv));
    const float n1  = fmaf(v10, Av, fmaf(v11, Bv, bv1 * Dv));

    out[base + w]          = fmaf(n0, inv, xa);
    out[n_elem + base + w] = fmaf(n1, inv, xb);
}

extern "C" void kernel_launch(void* const* d_in, const int* in_sizes, int n_in,
                              void* d_out, int out_size)
{
    const float* x1 = (const float*)d_in[0];
    const float* x2 = (const float*)d_in[1];
    const float* wq = (const float*)d_in[2];
    const float* bq = (const float*)d_in[3];
    const float* wk = (const float*)d_in[4];
    const float* bk = (const float*)d_in[5];
    const float* wv = (const float*)d_in[6];
    const float* bv = (const float*)d_in[7];
    float* out = (float*)d_out;

    const int n_elem = in_sizes[0];        // B*H*W = 524288
    const int rows   = n_elem / WIDTH;     // B*H   = 2048

    channel_attn_kernel<<<rows, WIDTH>>>(x1, x2, wq, bq, wk, bk, wv, bv,
                                         out, n_elem);
}